// round 14
// baseline (speedup 1.0000x reference)
#include <cuda_runtime.h>
#include <cuda_bf16.h>
#include <math_constants.h>

#define MAXN 50000
#define MAXE 400000
#define NUM_GRAPHS 64
#define BN 32   // nodes per block
#define NT 4    // nodes per GEMM thread

// Padded feature strides (multiples of 4)
#define FP1 76
#define FP2 152
#define FP3 52

// Scratch: device globals, referenced ONLY from device code.
__device__ float g_dinv[MAXN];
__device__ int   g_count[MAXN];
__device__ int   g_rowptr[MAXN];
__device__ int   g_cursor[MAXN];
__device__ int   g_col[MAXE];
__device__ float g_w[MAXE];
__device__ float g_linA[MAXN * FP1];   // layer1 lin (FP1); reused for layer3 out (FP3)
__device__ float g_linB[MAXN * FP2];   // layer2 lin (FP2)
__device__ float g_pool[NUM_GRAPHS * 3];
__device__ int   g_total;
__device__ int   g_woIsC0;

// ---------------------------------------------------------------------------
__global__ void k_init(const float* __restrict__ c0, int N) {
    int i = blockIdx.x * blockDim.x + threadIdx.x;
    if (i < N) g_count[i] = 0;
    if (i < NUM_GRAPHS * 3) g_pool[i] = -CUDART_INF_F;
    if (i == N) {
        g_total = 0;
        float s = 0.0f;
        for (int k = 0; k < 150; k++) s += fabsf(c0[k]);
        g_woIsC0 = (s > 0.0f) ? 1 : 0;
    }
}

__global__ void k_hist(const int* __restrict__ dst, int E, int N) {
    int e = blockIdx.x * blockDim.x + threadIdx.x;
    if (e >= E) return;
    unsigned d = (unsigned)dst[e];
    if (d < (unsigned)N) atomicAdd(&g_count[d], 1);
}

// Warp-aggregated CSR segment allocation (segment order arbitrary).
__global__ void k_alloc(int N) {
    int i = blockIdx.x * blockDim.x + threadIdx.x;
    int lane = threadIdx.x & 31;
    int v = (i < N) ? g_count[i] : 0;
    int incl = v;
    #pragma unroll
    for (int off = 1; off < 32; off <<= 1) {
        int t = __shfl_up_sync(0xFFFFFFFFu, incl, off);
        if (lane >= off) incl += t;
    }
    int wtot = __shfl_sync(0xFFFFFFFFu, incl, 31);
    int base = 0;
    if (lane == 0) base = atomicAdd(&g_total, wtot);
    base = __shfl_sync(0xFFFFFFFFu, base, 0);
    if (i < N) {
        int r = base + incl - v;  // exclusive within warp + warp base
        g_rowptr[i] = r;
        g_cursor[i] = r;
        g_dinv[i] = rsqrtf((float)(v + 1));  // +1 self-loop
    }
}

__global__ void k_fill(const int* __restrict__ src, const int* __restrict__ dst,
                       int E, int N) {
    int e = blockIdx.x * blockDim.x + threadIdx.x;
    if (e >= E) return;
    unsigned s = (unsigned)src[e];
    unsigned d = (unsigned)dst[e];
    if (s >= (unsigned)N || d >= (unsigned)N) return;
    int pos = atomicAdd(&g_cursor[d], 1);
    g_col[pos] = (int)s;
    g_w[pos] = g_dinv[s];
}

// ---------------------------------------------------------------------------
// Layer-1 GEMM: x (stride 36, external) @ W1 -> g_linA (stride FP1).
__global__ void k_gemm1(const float* __restrict__ x, const float* __restrict__ W,
                        int N) {
    constexpr int K = 36, KP = 36, M = 75, MP = FP1;
    extern __shared__ float Ws[];
    for (int i = threadIdx.x; i < KP * MP; i += blockDim.x) {
        int k = i / MP, m = i - k * MP;
        Ws[i] = (k < K && m < M) ? W[k * M + m] : 0.0f;
    }
    __syncthreads();
    constexpr int C = MP >> 2;
    const int nodeBase = blockIdx.x * BN;
    constexpr int ngroups = BN / NT;
    for (int t = threadIdx.x; t < ngroups * C; t += blockDim.x) {
        int g = t / C, c = t - g * C, m0 = c << 2;
        int n0 = nodeBase + g * NT;
        const float4* r[NT];
        #pragma unroll
        for (int i = 0; i < NT; i++)
            r[i] = (const float4*)(x + (long)min(n0 + i, N - 1) * KP);
        float4 a[NT];
        #pragma unroll
        for (int i = 0; i < NT; i++) a[i] = make_float4(0.f, 0.f, 0.f, 0.f);
        #pragma unroll
        for (int k4 = 0; k4 < (KP >> 2); k4++) {
            float4 v[NT];
            #pragma unroll
            for (int i = 0; i < NT; i++) v[i] = r[i][k4];
            int kb = k4 << 2;
            #pragma unroll
            for (int kk = 0; kk < 4; kk++) {
                float4 w = *(const float4*)&Ws[(kb + kk) * MP + m0];
                #pragma unroll
                for (int i = 0; i < NT; i++) {
                    float s = (kk == 0) ? v[i].x : (kk == 1) ? v[i].y : (kk == 2) ? v[i].z : v[i].w;
                    a[i].x = fmaf(s, w.x, a[i].x); a[i].y = fmaf(s, w.y, a[i].y);
                    a[i].z = fmaf(s, w.z, a[i].z); a[i].w = fmaf(s, w.w, a[i].w);
                }
            }
        }
        #pragma unroll
        for (int i = 0; i < NT; i++)
            if (n0 + i < N) ((float4*)(g_linA + (long)(n0 + i) * MP))[c] = a[i];
    }
}

// ---------------------------------------------------------------------------
// Fused warp-per-node gather-aggregate (+bias+relu into smem) then GEMM.
// Gather: warp owns a node; lanes = float4 chunks of the row. Edge metadata
// (g_col/g_w) loads are warp-uniform (single broadcast); neighbor rows are
// read as consecutive float4s by adjacent lanes (coalesced).
template <int KP, int K, int MP, int M, int BSEL>
__global__ void k_aggemm(const float* __restrict__ W, const float* __restrict__ bias,
                         const float* __restrict__ c0, const float* __restrict__ c1,
                         int srcIsA, int N) {
    extern __shared__ float smem[];
    float* Ws = smem;                 // KP*MP
    float* h  = smem + KP * MP;       // BN*KP
    for (int i = threadIdx.x; i < KP * MP; i += blockDim.x) {
        int k = i / MP, m = i - k * MP;
        Ws[i] = (k < K && m < M) ? W[k * M + m] : 0.0f;
    }
    const float* lin = srcIsA ? (const float*)g_linA : (const float*)g_linB;
    const float4* lin4 = (const float4*)lin;
    const float* b = bias;
    if (BSEL) b = g_woIsC0 ? c1 : c0;

    constexpr int Cin = KP >> 2;
    constexpr int CPL = (Cin + 31) / 32;   // chunks per lane
    const int nodeBase = blockIdx.x * BN;
    const int wrp = threadIdx.x >> 5;
    const int lane = threadIdx.x & 31;
    const int nW = blockDim.x >> 5;

    for (int ln = wrp; ln < BN; ln += nW) {
        int n = nodeBase + ln;
        float4 o[CPL];
        #pragma unroll
        for (int p = 0; p < CPL; p++) o[p] = make_float4(0.f, 0.f, 0.f, 0.f);
        if (n < N) {
            float4 acc[CPL];
            #pragma unroll
            for (int p = 0; p < CPL; p++) acc[p] = make_float4(0.f, 0.f, 0.f, 0.f);
            int beg = g_rowptr[n], cnt = g_count[n];
            for (int j = beg; j < beg + cnt; j++) {
                int s = g_col[j];      // warp-uniform
                float ws = g_w[j];     // warp-uniform
                const float4* row = lin4 + (long)s * Cin;
                #pragma unroll
                for (int p = 0; p < CPL; p++) {
                    int c = lane + 32 * p;
                    if (c < Cin) {
                        float4 v = row[c];
                        acc[p].x = fmaf(ws, v.x, acc[p].x);
                        acc[p].y = fmaf(ws, v.y, acc[p].y);
                        acc[p].z = fmaf(ws, v.z, acc[p].z);
                        acc[p].w = fmaf(ws, v.w, acc[p].w);
                    }
                }
            }
            float dn = g_dinv[n], dn2 = dn * dn;
            const float4* srow = lin4 + (long)n * Cin;
            #pragma unroll
            for (int p = 0; p < CPL; p++) {
                int c = lane + 32 * p;
                if (c < Cin) {
                    float4 self = srow[c];
                    int f0 = c << 2;
                    o[p].x = fmaxf(fmaf(dn, acc[p].x, dn2 * self.x) + ((f0 + 0 < K) ? b[f0 + 0] : 0.f), 0.f);
                    o[p].y = fmaxf(fmaf(dn, acc[p].y, dn2 * self.y) + ((f0 + 1 < K) ? b[f0 + 1] : 0.f), 0.f);
                    o[p].z = fmaxf(fmaf(dn, acc[p].z, dn2 * self.z) + ((f0 + 2 < K) ? b[f0 + 2] : 0.f), 0.f);
                    o[p].w = fmaxf(fmaf(dn, acc[p].w, dn2 * self.w) + ((f0 + 3 < K) ? b[f0 + 3] : 0.f), 0.f);
                }
            }
        }
        #pragma unroll
        for (int p = 0; p < CPL; p++) {
            int c = lane + 32 * p;
            if (c < Cin) *(float4*)&h[ln * KP + (c << 2)] = o[p];
        }
    }
    __syncthreads();

    float* outLin = srcIsA ? (float*)g_linB : (float*)g_linA;
    constexpr int Cout = MP >> 2;
    constexpr int ngroups = BN / NT;
    for (int t = threadIdx.x; t < ngroups * Cout; t += blockDim.x) {
        int g = t / Cout, c = t - g * Cout, m0 = c << 2;
        int n0 = nodeBase + g * NT;
        float4 a[NT];
        #pragma unroll
        for (int i = 0; i < NT; i++) a[i] = make_float4(0.f, 0.f, 0.f, 0.f);
        for (int k4 = 0; k4 < (KP >> 2); k4++) {
            float4 v[NT];
            #pragma unroll
            for (int i = 0; i < NT; i++)
                v[i] = *(const float4*)&h[(g * NT + i) * KP + (k4 << 2)];
            int kb = k4 << 2;
            #pragma unroll
            for (int kk = 0; kk < 4; kk++) {
                float4 w = *(const float4*)&Ws[(kb + kk) * MP + m0];
                #pragma unroll
                for (int i = 0; i < NT; i++) {
                    float s = (kk == 0) ? v[i].x : (kk == 1) ? v[i].y : (kk == 2) ? v[i].z : v[i].w;
                    a[i].x = fmaf(s, w.x, a[i].x); a[i].y = fmaf(s, w.y, a[i].y);
                    a[i].z = fmaf(s, w.z, a[i].z); a[i].w = fmaf(s, w.w, a[i].w);
                }
            }
        }
        #pragma unroll
        for (int i = 0; i < NT; i++)
            if (n0 + i < N) ((float4*)(outLin + (long)(n0 + i) * MP))[c] = a[i];
    }
}

// ---------------------------------------------------------------------------
__device__ __forceinline__ void atomicMaxFloat(float* addr, float val) {
    if (val >= 0.0f)
        atomicMax((int*)addr, __float_as_int(val));
    else
        atomicMin((unsigned int*)addr, __float_as_uint(val));
}

// Fused layer-3 aggregate (warp-per-node) + projection + max-pool.
__global__ void k_finalagg(const float* __restrict__ c0, const float* __restrict__ c1,
                           const float* __restrict__ b3, const float* __restrict__ bo,
                           const int* __restrict__ batch, int N) {
    constexpr int KP = FP3, K = 50;
    constexpr int Cin = KP >> 2;   // 13
    __shared__ float h[BN * KP];
    __shared__ float Wos[KP * 3];
    const float* Wo = g_woIsC0 ? c0 : c1;
    for (int i = threadIdx.x; i < KP * 3; i += blockDim.x)
        Wos[i] = (i < K * 3) ? Wo[i] : 0.0f;

    const float4* lin4 = (const float4*)g_linA;
    const int nodeBase = blockIdx.x * BN;
    const int wrp = threadIdx.x >> 5;
    const int lane = threadIdx.x & 31;
    const int nW = blockDim.x >> 5;

    for (int ln = wrp; ln < BN; ln += nW) {
        int n = nodeBase + ln;
        float4 o = make_float4(0.f, 0.f, 0.f, 0.f);
        if (n < N && lane < Cin) {
            float4 acc = make_float4(0.f, 0.f, 0.f, 0.f);
            int beg = g_rowptr[n], cnt = g_count[n];
            for (int j = beg; j < beg + cnt; j++) {
                int s = g_col[j];
                float ws = g_w[j];
                float4 v = lin4[(long)s * Cin + lane];
                acc.x = fmaf(ws, v.x, acc.x); acc.y = fmaf(ws, v.y, acc.y);
                acc.z = fmaf(ws, v.z, acc.z); acc.w = fmaf(ws, v.w, acc.w);
            }
            float dn = g_dinv[n], dn2 = dn * dn;
            float4 self = lin4[(long)n * Cin + lane];
            int f0 = lane << 2;
            o.x = fmaxf(fmaf(dn, acc.x, dn2 * self.x) + ((f0 + 0 < K) ? b3[f0 + 0] : 0.f), 0.f);
            o.y = fmaxf(fmaf(dn, acc.y, dn2 * self.y) + ((f0 + 1 < K) ? b3[f0 + 1] : 0.f), 0.f);
            o.z = fmaxf(fmaf(dn, acc.z, dn2 * self.z) + ((f0 + 2 < K) ? b3[f0 + 2] : 0.f), 0.f);
            o.w = fmaxf(fmaf(dn, acc.w, dn2 * self.w) + ((f0 + 3 < K) ? b3[f0 + 3] : 0.f), 0.f);
        }
        if (lane < Cin) *(float4*)&h[ln * KP + (lane << 2)] = o;
    }
    __syncthreads();

    int ln = threadIdx.x;
    if (ln < BN) {
        int n = nodeBase + ln;
        if (n < N) {
            float a0 = bo[0], a1 = bo[1], a2 = bo[2];
            const float* row = &h[ln * KP];
            #pragma unroll
            for (int k = 0; k < K; k++) {
                float v = row[k];
                a0 = fmaf(v, Wos[k * 3 + 0], a0);
                a1 = fmaf(v, Wos[k * 3 + 1], a1);
                a2 = fmaf(v, Wos[k * 3 + 2], a2);
            }
            unsigned g = (unsigned)batch[n];
            if (g < NUM_GRAPHS) {
                atomicMaxFloat(&g_pool[g * 3 + 0], a0);
                atomicMaxFloat(&g_pool[g * 3 + 1], a1);
                atomicMaxFloat(&g_pool[g * 3 + 2], a2);
            }
        }
    }
}

__global__ void k_softmax(float* __restrict__ out) {
    int g = threadIdx.x;
    if (g >= NUM_GRAPHS) return;
    float p0 = g_pool[g * 3 + 0], p1 = g_pool[g * 3 + 1], p2 = g_pool[g * 3 + 2];
    float m = fmaxf(p0, fmaxf(p1, p2));
    float e0 = __expf(p0 - m), e1 = __expf(p1 - m), e2 = __expf(p2 - m);
    float inv = 1.0f / (e0 + e1 + e2);
    out[g * 3 + 0] = e0 * inv;
    out[g * 3 + 1] = e1 * inv;
    out[g * 3 + 2] = e2 * inv;
}

// ---------------------------------------------------------------------------
extern "C" void kernel_launch(void* const* d_in, const int* in_sizes, int n_in,
                              void* d_out, int out_size) {
    const float* x = nullptr;
    const int *ei = nullptr, *batch = nullptr;
    const float *W1 = nullptr, *W2 = nullptr, *W3 = nullptr;
    const float *b1 = nullptr, *b3 = nullptr, *bo = nullptr;
    const float *c150_0 = nullptr, *c150_1 = nullptr;

    for (int i = 0; i < n_in; i++) {
        const void* p = d_in[i];
        switch (in_sizes[i]) {
            case 1800000: x = (const float*)p; break;
            case 800000:  ei = (const int*)p; break;
            case 50000:   batch = (const int*)p; break;
            case 2700:    W1 = (const float*)p; break;
            case 11250:   W2 = (const float*)p; break;
            case 7500:    W3 = (const float*)p; break;
            case 75:      b1 = (const float*)p; break;
            case 50:      b3 = (const float*)p; break;
            case 3:       bo = (const float*)p; break;
            case 150:     if (!c150_0) c150_0 = (const float*)p;
                          else          c150_1 = (const float*)p;
                          break;
            default: break;
        }
    }
    if (!x || !ei || !batch || !W1 || !W2 || !W3 || !b1 || !b3 || !bo || !c150_0 || !c150_1) {
        x  = (const float*)d_in[0];
        ei = (const int*)d_in[1];
        batch = (const int*)d_in[2];
        W1 = (const float*)d_in[3];  b1 = (const float*)d_in[4];
        W2 = (const float*)d_in[5];  c150_1 = (const float*)d_in[6];
        W3 = (const float*)d_in[7];  b3 = (const float*)d_in[8];
        c150_0 = (const float*)d_in[9];
        bo = (const float*)d_in[10];
    }

    float* out = (float*)d_out;
    const int N = 50000;
    const int E = 400000;
    const int* src = ei;
    const int* dst = ei + E;

    const int T = 256;
    auto cdiv = [](long long a, long long b) { return (int)((a + b - 1) / b); };
    const int nbNode = cdiv(N, BN);

    const int SM2 = (FP1 * FP2 + BN * FP1) * (int)sizeof(float);  // ~55.9 KB
    const int SM3 = (FP2 * FP3 + BN * FP2) * (int)sizeof(float);  // ~51.1 KB

    static bool s_attr = false;
    if (!s_attr) {
        s_attr = true;
        cudaFuncSetAttribute((const void*)k_aggemm<FP1, 75, FP2, 150, 0>,
                             cudaFuncAttributeMaxDynamicSharedMemorySize, SM2);
        cudaFuncSetAttribute((const void*)k_aggemm<FP2, 150, FP3, 50, 1>,
                             cudaFuncAttributeMaxDynamicSharedMemorySize, SM3);
    }

    // Preprocessing: CSR by dst (arbitrary segment order).
    k_init<<<cdiv(N + 1, T), T>>>(c150_0, N);
    k_hist<<<cdiv(E, T), T>>>(dst, E, N);
    k_alloc<<<cdiv(N, T), T>>>(N);
    k_fill<<<cdiv(E, T), T>>>(src, dst, E, N);

    // Layer 1 GEMM: x @ W1 -> linA
    k_gemm1<<<nbNode, T, 36 * FP1 * sizeof(float)>>>(x, W1, N);

    // Layer 2: gather(linA) + b1 + relu -> smem -> @W2 -> linB
    k_aggemm<FP1, 75, FP2, 150, 0><<<nbNode, T, SM2>>>(W2, b1, nullptr, nullptr, 1, N);

    // Layer 3: gather(linB) + b2 + relu -> smem -> @W3 -> linA  (b2 = non-Wo 150-pair)
    k_aggemm<FP2, 150, FP3, 50, 1><<<nbNode, T, SM3>>>(W3, nullptr, c150_0, c150_1, 0, N);

    // Final: gather(linA) + b3 + relu -> project Wo + bo -> max-pool
    k_finalagg<<<nbNode, T>>>(c150_0, c150_1, b3, bo, batch, N);
    k_softmax<<<1, 64>>>(out);
}